// round 7
// baseline (speedup 1.0000x reference)
#include <cuda_runtime.h>

#define NMAX 100000
#define EMAX 3200000

// -------- device scratch (no allocations allowed) --------
__device__ int   g_deg[NMAX];          // per-node in-degree (excl self-loop)
__device__ int   g_start[NMAX];        // CSR row start
__device__ int   g_cursor[NMAX];       // fill cursors
__device__ int   g_adj[EMAX];          // CSR adjacency: src indices grouped by dst
__device__ float g_dinv[NMAX];         // 1/sqrt(deg+1)
__device__ __align__(16) float g_ht1[NMAX * 16];  // dinv * (x@W1)
__device__ __align__(16) float g_ht2[NMAX * 16];  // dinv * relu(agg1+b1)
__device__ float g_s1[NMAX];           // z . We[:64]
__device__ float g_s2[NMAX];           // z . We[64:]
__device__ float g_v1[16];             // W2 @ We[:64]
__device__ float g_v2[16];             // W2 @ We[64:]
__device__ float g_c1, g_c2;           // b2 . We halves

// decoupled-lookback scan state
__device__ volatile int g_agg[512];
__device__ volatile int g_pref[512];
__device__ volatile int g_flag[512];   // 0=none, 1=agg ready, 2=prefix ready

// -------- zero degrees + scan flags + fold W2/b2 into the edge head --------
__global__ void k_predeg(const float* __restrict__ W2, const float* __restrict__ b2,
                         const float* __restrict__ We, int n) {
    int i = blockIdx.x * blockDim.x + threadIdx.x;
    if (i < n) g_deg[i] = 0;
    if (i < 512) g_flag[i] = 0;
    if (blockIdx.x == 0) {
        int t = threadIdx.x;
        if (t < 16) {
            float a = 0.f, b = 0.f;
            #pragma unroll
            for (int j = 0; j < 64; j++) {
                float w = W2[t * 64 + j];
                a += w * We[j];
                b += w * We[64 + j];
            }
            g_v1[t] = a;
            g_v2[t] = b;
        } else if (t == 16) {
            float a = 0.f, b = 0.f;
            #pragma unroll
            for (int j = 0; j < 64; j++) {
                a += b2[j] * We[j];
                b += b2[j] * We[64 + j];
            }
            g_c1 = a;
            g_c2 = b;
        }
    }
}

__global__ void k_deg_acc(const int* __restrict__ dst, int E, int n) {
    int e = blockIdx.x * blockDim.x + threadIdx.x;
    if (e < E) {
        unsigned d = (unsigned)dst[e];
        if (d < (unsigned)n) atomicAdd(&g_deg[d], 1);
    }
}

// -------- single-pass exclusive scan (decoupled lookback) + dinv + cursors --------
__global__ void k_scan(int n) {
    __shared__ int s[256];
    __shared__ int s_run;
    int tid = threadIdx.x;
    int b = blockIdx.x;
    int i = b * 256 + tid;
    int deg = (i < n) ? g_deg[i] : 0;
    s[tid] = deg;
    __syncthreads();
    #pragma unroll
    for (int o = 1; o < 256; o <<= 1) {
        int t = (tid >= o) ? s[tid - o] : 0;
        __syncthreads();
        s[tid] += t;
        __syncthreads();
    }
    int incl = s[tid];
    int bsum = s[255];

    if (tid == 0) {
        if (b == 0) {
            g_pref[0] = bsum;
            __threadfence();
            g_flag[0] = 2;
            s_run = 0;
        } else {
            g_agg[b] = bsum;
            __threadfence();
            g_flag[b] = 1;
            int run = 0;
            int j = b - 1;
            while (true) {
                int f;
                while ((f = g_flag[j]) == 0) { }
                if (f == 2) { run += g_pref[j]; break; }
                run += g_agg[j];
                j--;
            }
            g_pref[b] = run + bsum;
            __threadfence();
            g_flag[b] = 2;
            s_run = run;
        }
    }
    __syncthreads();
    int run = s_run;
    if (i < n) {
        int st = run + incl - deg;   // exclusive
        g_start[i] = st;
        g_cursor[i] = st;
        g_dinv[i] = rsqrtf((float)deg + 1.0f);   // +1 = self-loop
    }
}

__global__ void k_fill(const int* __restrict__ src, const int* __restrict__ dst,
                       int E, int n) {
    int e = blockIdx.x * blockDim.x + threadIdx.x;
    if (e >= E) return;
    unsigned s = (unsigned)src[e];
    unsigned d = (unsigned)dst[e];
    if (s >= (unsigned)n || d >= (unsigned)n) return;
    int slot = atomicAdd(&g_cursor[d], 1);
    g_adj[slot] = (int)s;
}

// -------- GEMM1: ht1 = dinv * (x @ W1)  (runs after scan; overlaps fill) --------
__global__ void k_gemm1(const float* __restrict__ x, const float* __restrict__ W1, int n) {
    __shared__ float4 Wss[512 * 4];   // W1[k][4q..4q+3]  (32 KB)
    for (int i = threadIdx.x; i < 2048; i += blockDim.x)
        Wss[i] = ((const float4*)W1)[i];
    __syncthreads();

    int r = blockIdx.x * blockDim.x + threadIdx.x;
    if (r >= n) return;

    float acc[16];
    #pragma unroll
    for (int j = 0; j < 16; j++) acc[j] = 0.f;

    const float4* xr = (const float4*)(x + (size_t)r * 512);
    #pragma unroll 4
    for (int k4 = 0; k4 < 128; k4++) {
        float4 xv = __ldg(&xr[k4]);
        #pragma unroll
        for (int kk = 0; kk < 4; kk++) {
            float xs = ((const float*)&xv)[kk];
            int kbase = (k4 * 4 + kk) * 4;
            #pragma unroll
            for (int q = 0; q < 4; q++) {
                float4 w = Wss[kbase + q];
                acc[q * 4 + 0] = fmaf(xs, w.x, acc[q * 4 + 0]);
                acc[q * 4 + 1] = fmaf(xs, w.y, acc[q * 4 + 1]);
                acc[q * 4 + 2] = fmaf(xs, w.z, acc[q * 4 + 2]);
                acc[q * 4 + 3] = fmaf(xs, w.w, acc[q * 4 + 3]);
            }
        }
    }

    float di = g_dinv[r];
    float4* hp = (float4*)(g_ht1 + (size_t)r * 16);
    #pragma unroll
    for (int q = 0; q < 4; q++)
        hp[q] = make_float4(acc[q * 4 + 0] * di, acc[q * 4 + 1] * di,
                            acc[q * 4 + 2] * di, acc[q * 4 + 3] * di);
}

// -------- gather: 4 threads per node (half = 32B row-half, par = edge parity) ----
__device__ __forceinline__ void gather_quarter(const float* __restrict__ ht, int d,
                                               int half, int par,
                                               float4& a0, float4& a1) {
    if (par == 0) {   // self-loop term once
        const float4* sp = (const float4*)(ht + (size_t)d * 16 + half * 8);
        a0 = __ldg(&sp[0]);
        a1 = __ldg(&sp[1]);
    } else {
        a0 = make_float4(0.f, 0.f, 0.f, 0.f);
        a1 = make_float4(0.f, 0.f, 0.f, 0.f);
    }
    int st = g_start[d];
    int end = st + g_deg[d];
    int e = st + par;
    // this thread's edges: e, e+2, e+4, ... ; unroll 4 (stride 8)
    for (; e + 6 < end; e += 8) {
        int s0 = __ldg(&g_adj[e]);
        int s1 = __ldg(&g_adj[e + 2]);
        int s2 = __ldg(&g_adj[e + 4]);
        int s3 = __ldg(&g_adj[e + 6]);
        const float4* p0 = (const float4*)(ht + (size_t)s0 * 16 + half * 8);
        const float4* p1 = (const float4*)(ht + (size_t)s1 * 16 + half * 8);
        const float4* p2 = (const float4*)(ht + (size_t)s2 * 16 + half * 8);
        const float4* p3 = (const float4*)(ht + (size_t)s3 * 16 + half * 8);
        float4 v00 = __ldg(&p0[0]), v01 = __ldg(&p0[1]);
        float4 v10 = __ldg(&p1[0]), v11 = __ldg(&p1[1]);
        float4 v20 = __ldg(&p2[0]), v21 = __ldg(&p2[1]);
        float4 v30 = __ldg(&p3[0]), v31 = __ldg(&p3[1]);
        a0.x += (v00.x + v10.x) + (v20.x + v30.x);
        a0.y += (v00.y + v10.y) + (v20.y + v30.y);
        a0.z += (v00.z + v10.z) + (v20.z + v30.z);
        a0.w += (v00.w + v10.w) + (v20.w + v30.w);
        a1.x += (v01.x + v11.x) + (v21.x + v31.x);
        a1.y += (v01.y + v11.y) + (v21.y + v31.y);
        a1.z += (v01.z + v11.z) + (v21.z + v31.z);
        a1.w += (v01.w + v11.w) + (v21.w + v31.w);
    }
    for (; e < end; e += 2) {
        int s0 = __ldg(&g_adj[e]);
        const float4* p0 = (const float4*)(ht + (size_t)s0 * 16 + half * 8);
        float4 v00 = __ldg(&p0[0]), v01 = __ldg(&p0[1]);
        a0.x += v00.x; a0.y += v00.y; a0.z += v00.z; a0.w += v00.w;
        a1.x += v01.x; a1.y += v01.y; a1.z += v01.z; a1.w += v01.w;
    }
}

__device__ __forceinline__ void par_combine(float4& a0, float4& a1) {
    a0.x += __shfl_xor_sync(0xffffffffu, a0.x, 1);
    a0.y += __shfl_xor_sync(0xffffffffu, a0.y, 1);
    a0.z += __shfl_xor_sync(0xffffffffu, a0.z, 1);
    a0.w += __shfl_xor_sync(0xffffffffu, a0.w, 1);
    a1.x += __shfl_xor_sync(0xffffffffu, a1.x, 1);
    a1.y += __shfl_xor_sync(0xffffffffu, a1.y, 1);
    a1.z += __shfl_xor_sync(0xffffffffu, a1.z, 1);
    a1.w += __shfl_xor_sync(0xffffffffu, a1.w, 1);
}

// -------- gather layer 1: ht2 = dinv * relu(dinv*sum + b1) --------
__global__ void k_gather1(const float* __restrict__ b1, int n) {
    int t = blockIdx.x * blockDim.x + threadIdx.x;
    int d = t >> 2, half = (t >> 1) & 1, par = t & 1;
    bool valid = (d < n);
    int dd = valid ? d : 0;
    float4 a0, a1;
    gather_quarter(g_ht1, dd, half, par, a0, a1);
    par_combine(a0, a1);
    if (!valid || par != 0) return;
    float di = g_dinv[d];
    const float4* bb = (const float4*)b1 + half * 2;
    float4 b0 = __ldg(&bb[0]), b1q = __ldg(&bb[1]);
    float4 h0, h1;
    h0.x = fmaxf(fmaf(a0.x, di, b0.x), 0.f) * di;
    h0.y = fmaxf(fmaf(a0.y, di, b0.y), 0.f) * di;
    h0.z = fmaxf(fmaf(a0.z, di, b0.z), 0.f) * di;
    h0.w = fmaxf(fmaf(a0.w, di, b0.w), 0.f) * di;
    h1.x = fmaxf(fmaf(a1.x, di, b1q.x), 0.f) * di;
    h1.y = fmaxf(fmaf(a1.y, di, b1q.y), 0.f) * di;
    h1.z = fmaxf(fmaf(a1.z, di, b1q.z), 0.f) * di;
    h1.w = fmaxf(fmaf(a1.w, di, b1q.w), 0.f) * di;
    float4* op = (float4*)(g_ht2 + (size_t)d * 16 + half * 8);
    op[0] = h0;
    op[1] = h1;
}

// -------- gather layer 2 + fused epilogue: z, s1, s2 --------
__global__ void k_gather2(const float* __restrict__ W2, const float* __restrict__ b2,
                          float* __restrict__ z, int n) {
    __shared__ float4 Ws[16 * 16];   // W2[k] column-quads (4 KB)
    __shared__ float4 bs[16];
    __shared__ float vs1[16], vs2[16];
    for (int i = threadIdx.x; i < 256; i += blockDim.x)
        Ws[i] = ((const float4*)W2)[i];
    if (threadIdx.x < 16) {
        bs[threadIdx.x] = ((const float4*)b2)[threadIdx.x];
        vs1[threadIdx.x] = g_v1[threadIdx.x];
        vs2[threadIdx.x] = g_v2[threadIdx.x];
    }
    __syncthreads();

    int t = blockIdx.x * blockDim.x + threadIdx.x;
    int d = t >> 2, half = (t >> 1) & 1, par = t & 1;
    bool valid = (d < n);
    int dd = valid ? d : 0;

    float4 a0, a1;
    gather_quarter(g_ht2, dd, half, par, a0, a1);
    par_combine(a0, a1);

    float di = g_dinv[dd];
    float mine[8];
    mine[0] = a0.x * di; mine[1] = a0.y * di; mine[2] = a0.z * di; mine[3] = a0.w * di;
    mine[4] = a1.x * di; mine[5] = a1.y * di; mine[6] = a1.z * di; mine[7] = a1.w * di;

    // exchange halves across the (t^2) partner: build full a[16] in every lane
    float a[16];
    #pragma unroll
    for (int j = 0; j < 8; j++) {
        a[half * 8 + j] = mine[j];
        a[(1 - half) * 8 + j] = __shfl_xor_sync(0xffffffffu, mine[j], 2);
    }

    if (!valid) return;

    // head scalars (one lane per node)
    if (half == 0 && par == 0) {
        float s1 = g_c1, s2 = g_c2;
        #pragma unroll
        for (int k = 0; k < 16; k++) {
            s1 = fmaf(a[k], vs1[k], s1);
            s2 = fmaf(a[k], vs2[k], s2);
        }
        g_s1[d] = s1;
        g_s2[d] = s2;
    }

    // z: each of the 4 lanes writes a 16-column quarter (4 float4 quads)
    int quarter = half * 2 + par;
    float4* zp = (float4*)(z + (size_t)d * 64) + quarter * 4;
    #pragma unroll
    for (int q = 0; q < 4; q++) {
        int j4 = quarter * 4 + q;
        float4 acc = bs[j4];
        #pragma unroll
        for (int k = 0; k < 16; k++) {
            float4 w = Ws[k * 16 + j4];
            acc.x = fmaf(a[k], w.x, acc.x);
            acc.y = fmaf(a[k], w.y, acc.y);
            acc.z = fmaf(a[k], w.z, acc.z);
            acc.w = fmaf(a[k], w.w, acc.w);
        }
        zp[q] = acc;
    }
}

// -------- edge logits: s1[src] + s2[dst] + be --------
__global__ void k_logits(const int* __restrict__ ps, const int* __restrict__ pd,
                         const int* __restrict__ ns, const int* __restrict__ nd,
                         const float* __restrict__ be, float* __restrict__ out,
                         int P, int Ng, int n) {
    int i = blockIdx.x * blockDim.x + threadIdx.x;
    if (i >= P + Ng) return;
    unsigned s, d;
    if (i < P) { s = (unsigned)ps[i]; d = (unsigned)pd[i]; }
    else       { s = (unsigned)ns[i - P]; d = (unsigned)nd[i - P]; }
    float v = __ldg(be);
    if (s < (unsigned)n) v += g_s1[s];
    if (d < (unsigned)n) v += g_s2[d];
    out[i] = v;
}

extern "C" void kernel_launch(void* const* d_in, const int* in_sizes, int n_in,
                              void* d_out, int out_size) {
    const float* x  = (const float*)d_in[0];
    const float* W1 = (const float*)d_in[1];
    const float* b1 = (const float*)d_in[2];
    const float* W2 = (const float*)d_in[3];
    const float* b2 = (const float*)d_in[4];
    const float* We = (const float*)d_in[5];
    const float* be = (const float*)d_in[6];
    const int* ei = (const int*)d_in[7];   // edge_index int32 [2, E]
    const int* pe = (const int*)d_in[8];   // pos_edge_index int32 [2, P]
    const int* ne = (const int*)d_in[9];   // neg_edge_index int32 [2, Ng]

    int n  = in_sizes[0] / 512;
    int E  = in_sizes[7] / 2;
    int P  = in_sizes[8] / 2;
    int Ng = in_sizes[9] / 2;

    float* z = (float*)d_out;                 // [n, 64]
    float* logits = z + (size_t)n * 64;       // [P + Ng]

    const int* src = ei;
    const int* dst = ei + E;

    int nb  = (n + 255) / 256;
    int eb  = (E + 255) / 256;
    int gb  = (4 * n + 255) / 256;
    int lb  = (P + Ng + 255) / 256;

    // One-time stream/event setup (outside capture: first call is uncaptured).
    static cudaStream_t s1 = nullptr;
    static cudaEvent_t evScan = nullptr, evG = nullptr;
    if (s1 == nullptr) {
        cudaStreamCreateWithFlags(&s1, cudaStreamNonBlocking);
        cudaEventCreateWithFlags(&evScan, cudaEventDisableTiming);
        cudaEventCreateWithFlags(&evG, cudaEventDisableTiming);
    }

    // Main: CSR build up to scan (produces dinv).
    k_predeg<<<nb, 256>>>(W2, b2, We, n);          // launch 1
    k_deg_acc<<<eb, 256>>>(dst, E, n);             // launch 2
    k_scan<<<nb, 256>>>(n);                        // launch 3

    // Fork: GEMM1 (needs dinv) overlaps fill on main.
    cudaEventRecord(evScan, 0);
    cudaStreamWaitEvent(s1, evScan, 0);
    k_gemm1<<<nb, 256, 0, s1>>>(x, W1, n);         // launch 4
    cudaEventRecord(evG, s1);

    k_fill<<<eb, 256>>>(src, dst, E, n);           // launch 5

    // Join: gathers need ht1 (gemm1) and adj (fill).
    cudaStreamWaitEvent(0, evG, 0);
    k_gather1<<<gb, 256>>>(b1, n);                 // launch 6 (ncu -s 5 target)
    k_gather2<<<gb, 256>>>(W2, b2, z, n);          // launch 7
    k_logits<<<lb, 256>>>(pe, pe + P, ne, ne + Ng, be, logits, P, Ng, n);  // launch 8
}

// round 8
// speedup vs baseline: 1.1057x; 1.1057x over previous
#include <cuda_runtime.h>

#define NMAX 100000
#define EMAX 3200000

// -------- device scratch (no allocations allowed) --------
__device__ int   g_deg[NMAX];          // per-node in-degree (excl self-loop)
__device__ int   g_start[NMAX];        // CSR row start
__device__ int   g_cursor[NMAX];       // fill cursors
__device__ int   g_adj[EMAX];          // CSR adjacency: src indices grouped by dst
__device__ float g_dinv[NMAX];         // 1/sqrt(deg+1)
__device__ __align__(16) float g_ht1[NMAX * 16];  // raw x@W1, then dinv-scaled
__device__ __align__(16) float g_ht2[NMAX * 16];  // dinv * relu(agg1+b1)
__device__ float g_s1[NMAX];           // z . We[:64]
__device__ float g_s2[NMAX];           // z . We[64:]
__device__ float g_v1[16];             // W2 @ We[:64]
__device__ float g_v2[16];             // W2 @ We[64:]
__device__ float g_c1, g_c2;           // b2 . We halves

// decoupled-lookback scan state
__device__ volatile int g_agg[512];
__device__ volatile int g_pref[512];
__device__ volatile int g_flag[512];   // 0=none, 1=agg ready, 2=prefix ready

// -------- zero degrees + scan flags + fold W2/b2 into the edge head --------
__global__ void k_predeg(const float* __restrict__ W2, const float* __restrict__ b2,
                         const float* __restrict__ We, int n) {
    int i = blockIdx.x * blockDim.x + threadIdx.x;
    if (i < n) g_deg[i] = 0;
    if (i < 512) g_flag[i] = 0;
    if (blockIdx.x == 0) {
        int t = threadIdx.x;
        if (t < 16) {
            float a = 0.f, b = 0.f;
            #pragma unroll
            for (int j = 0; j < 64; j++) {
                float w = W2[t * 64 + j];
                a += w * We[j];
                b += w * We[64 + j];
            }
            g_v1[t] = a;
            g_v2[t] = b;
        } else if (t == 16) {
            float a = 0.f, b = 0.f;
            #pragma unroll
            for (int j = 0; j < 64; j++) {
                a += b2[j] * We[j];
                b += b2[j] * We[64 + j];
            }
            g_c1 = a;
            g_c2 = b;
        }
    }
}

__global__ void k_deg_acc(const int* __restrict__ dst, int E, int n) {
    int e = blockIdx.x * blockDim.x + threadIdx.x;
    if (e < E) {
        unsigned d = (unsigned)dst[e];
        if (d < (unsigned)n) atomicAdd(&g_deg[d], 1);
    }
}

// -------- single-pass exclusive scan (decoupled lookback) + dinv + cursors --------
__global__ void k_scan(int n) {
    __shared__ int s[256];
    __shared__ int s_run;
    int tid = threadIdx.x;
    int b = blockIdx.x;
    int i = b * 256 + tid;
    int deg = (i < n) ? g_deg[i] : 0;
    s[tid] = deg;
    __syncthreads();
    #pragma unroll
    for (int o = 1; o < 256; o <<= 1) {
        int t = (tid >= o) ? s[tid - o] : 0;
        __syncthreads();
        s[tid] += t;
        __syncthreads();
    }
    int incl = s[tid];
    int bsum = s[255];

    if (tid == 0) {
        if (b == 0) {
            g_pref[0] = bsum;
            __threadfence();
            g_flag[0] = 2;
            s_run = 0;
        } else {
            g_agg[b] = bsum;
            __threadfence();
            g_flag[b] = 1;
            int run = 0;
            int j = b - 1;
            while (true) {
                int f;
                while ((f = g_flag[j]) == 0) { }
                if (f == 2) { run += g_pref[j]; break; }
                run += g_agg[j];
                j--;
            }
            g_pref[b] = run + bsum;
            __threadfence();
            g_flag[b] = 2;
            s_run = run;
        }
    }
    __syncthreads();
    int run = s_run;
    if (i < n) {
        int st = run + incl - deg;   // exclusive
        g_start[i] = st;
        g_cursor[i] = st;
        g_dinv[i] = rsqrtf((float)deg + 1.0f);   // +1 = self-loop
    }
}

__global__ void k_fill(const int* __restrict__ src, const int* __restrict__ dst,
                       int E, int n) {
    int e = blockIdx.x * blockDim.x + threadIdx.x;
    if (e >= E) return;
    unsigned s = (unsigned)src[e];
    unsigned d = (unsigned)dst[e];
    if (s >= (unsigned)n || d >= (unsigned)n) return;
    int slot = atomicAdd(&g_cursor[d], 1);
    g_adj[slot] = (int)s;
}

// -------- GEMM1: ht1 = x @ W1 (raw), coalesced via smem x-tiles --------
// 256 rows/block, k-tile 8. x-tile rows padded to 12 floats: quad bank-groups
// (3*lane + q) & 7 are distinct within each 8-lane phase -> conflict-free.
__global__ void __launch_bounds__(256) k_gemm1(const float* __restrict__ x,
                                               const float* __restrict__ W1, int n) {
    __shared__ float4 Wss[2048];        // W1[k][4q..4q+3], broadcast reads (32 KB)
    __shared__ float  xs[256 * 12];     // 12 KB padded x tile
    for (int i = threadIdx.x; i < 2048; i += 256)
        Wss[i] = ((const float4*)W1)[i];

    int row0 = blockIdx.x * 256;
    int tid = threadIdx.x;

    float acc[16];
    #pragma unroll
    for (int j = 0; j < 16; j++) acc[j] = 0.f;

    const float4* xq = (const float4*)x;

    for (int kt = 0; kt < 64; kt++) {
        __syncthreads();   // xs reuse barrier (and W ready on first iter)
        // load tile rows [row0, row0+256) cols [kt*8, kt*8+8): 512 quads, 2/thread
        #pragma unroll
        for (int m = 0; m < 2; m++) {
            int idx = tid + m * 256;
            int rr = idx >> 1, q = idx & 1;
            int grow = row0 + rr;
            float4 v = make_float4(0.f, 0.f, 0.f, 0.f);
            if (grow < n) v = __ldg(&xq[(size_t)grow * 128 + kt * 2 + q]);
            *(float4*)&xs[rr * 12 + q * 4] = v;
        }
        __syncthreads();

        float4 x0 = *(const float4*)&xs[tid * 12];
        float4 x1 = *(const float4*)&xs[tid * 12 + 4];
        float xv[8] = {x0.x, x0.y, x0.z, x0.w, x1.x, x1.y, x1.z, x1.w};
        #pragma unroll
        for (int kk = 0; kk < 8; kk++) {
            int k = kt * 8 + kk;
            float xsv = xv[kk];
            #pragma unroll
            for (int q2 = 0; q2 < 4; q2++) {
                float4 w = Wss[k * 4 + q2];
                acc[q2 * 4 + 0] = fmaf(xsv, w.x, acc[q2 * 4 + 0]);
                acc[q2 * 4 + 1] = fmaf(xsv, w.y, acc[q2 * 4 + 1]);
                acc[q2 * 4 + 2] = fmaf(xsv, w.z, acc[q2 * 4 + 2]);
                acc[q2 * 4 + 3] = fmaf(xsv, w.w, acc[q2 * 4 + 3]);
            }
        }
    }

    int r = row0 + tid;
    if (r < n) {
        float4* hp = (float4*)(g_ht1 + (size_t)r * 16);
        #pragma unroll
        for (int q = 0; q < 4; q++)
            hp[q] = make_float4(acc[q * 4 + 0], acc[q * 4 + 1],
                                acc[q * 4 + 2], acc[q * 4 + 3]);
    }
}

// -------- scale: ht1 *= dinv (join of gemm1 stream and CSR chain) --------
__global__ void k_scale(int n) {
    int i = blockIdx.x * blockDim.x + threadIdx.x;
    if (i >= n) return;
    float di = g_dinv[i];
    float4* p = (float4*)(g_ht1 + (size_t)i * 16);
    #pragma unroll
    for (int q = 0; q < 4; q++) {
        float4 v = p[q];
        p[q] = make_float4(v.x * di, v.y * di, v.z * di, v.w * di);
    }
}

// -------- gather: 4 threads per node (half = 32B row-half, par = edge parity) ----
__device__ __forceinline__ void gather_quarter(const float* __restrict__ ht, int d,
                                               int half, int par,
                                               float4& a0, float4& a1) {
    if (par == 0) {   // self-loop term once
        const float4* sp = (const float4*)(ht + (size_t)d * 16 + half * 8);
        a0 = __ldg(&sp[0]);
        a1 = __ldg(&sp[1]);
    } else {
        a0 = make_float4(0.f, 0.f, 0.f, 0.f);
        a1 = make_float4(0.f, 0.f, 0.f, 0.f);
    }
    int st = g_start[d];
    int end = st + g_deg[d];
    int e = st + par;
    for (; e + 6 < end; e += 8) {
        int s0 = __ldg(&g_adj[e]);
        int s1 = __ldg(&g_adj[e + 2]);
        int s2 = __ldg(&g_adj[e + 4]);
        int s3 = __ldg(&g_adj[e + 6]);
        const float4* p0 = (const float4*)(ht + (size_t)s0 * 16 + half * 8);
        const float4* p1 = (const float4*)(ht + (size_t)s1 * 16 + half * 8);
        const float4* p2 = (const float4*)(ht + (size_t)s2 * 16 + half * 8);
        const float4* p3 = (const float4*)(ht + (size_t)s3 * 16 + half * 8);
        float4 v00 = __ldg(&p0[0]), v01 = __ldg(&p0[1]);
        float4 v10 = __ldg(&p1[0]), v11 = __ldg(&p1[1]);
        float4 v20 = __ldg(&p2[0]), v21 = __ldg(&p2[1]);
        float4 v30 = __ldg(&p3[0]), v31 = __ldg(&p3[1]);
        a0.x += (v00.x + v10.x) + (v20.x + v30.x);
        a0.y += (v00.y + v10.y) + (v20.y + v30.y);
        a0.z += (v00.z + v10.z) + (v20.z + v30.z);
        a0.w += (v00.w + v10.w) + (v20.w + v30.w);
        a1.x += (v01.x + v11.x) + (v21.x + v31.x);
        a1.y += (v01.y + v11.y) + (v21.y + v31.y);
        a1.z += (v01.z + v11.z) + (v21.z + v31.z);
        a1.w += (v01.w + v11.w) + (v21.w + v31.w);
    }
    for (; e < end; e += 2) {
        int s0 = __ldg(&g_adj[e]);
        const float4* p0 = (const float4*)(ht + (size_t)s0 * 16 + half * 8);
        float4 v00 = __ldg(&p0[0]), v01 = __ldg(&p0[1]);
        a0.x += v00.x; a0.y += v00.y; a0.z += v00.z; a0.w += v00.w;
        a1.x += v01.x; a1.y += v01.y; a1.z += v01.z; a1.w += v01.w;
    }
}

__device__ __forceinline__ void par_combine(float4& a0, float4& a1) {
    a0.x += __shfl_xor_sync(0xffffffffu, a0.x, 1);
    a0.y += __shfl_xor_sync(0xffffffffu, a0.y, 1);
    a0.z += __shfl_xor_sync(0xffffffffu, a0.z, 1);
    a0.w += __shfl_xor_sync(0xffffffffu, a0.w, 1);
    a1.x += __shfl_xor_sync(0xffffffffu, a1.x, 1);
    a1.y += __shfl_xor_sync(0xffffffffu, a1.y, 1);
    a1.z += __shfl_xor_sync(0xffffffffu, a1.z, 1);
    a1.w += __shfl_xor_sync(0xffffffffu, a1.w, 1);
}

// -------- gather layer 1: ht2 = dinv * relu(dinv*sum + b1) --------
__global__ void k_gather1(const float* __restrict__ b1, int n) {
    int t = blockIdx.x * blockDim.x + threadIdx.x;
    int d = t >> 2, half = (t >> 1) & 1, par = t & 1;
    bool valid = (d < n);
    int dd = valid ? d : 0;
    float4 a0, a1;
    gather_quarter(g_ht1, dd, half, par, a0, a1);
    par_combine(a0, a1);
    if (!valid || par != 0) return;
    float di = g_dinv[d];
    const float4* bb = (const float4*)b1 + half * 2;
    float4 b0 = __ldg(&bb[0]), b1q = __ldg(&bb[1]);
    float4 h0, h1;
    h0.x = fmaxf(fmaf(a0.x, di, b0.x), 0.f) * di;
    h0.y = fmaxf(fmaf(a0.y, di, b0.y), 0.f) * di;
    h0.z = fmaxf(fmaf(a0.z, di, b0.z), 0.f) * di;
    h0.w = fmaxf(fmaf(a0.w, di, b0.w), 0.f) * di;
    h1.x = fmaxf(fmaf(a1.x, di, b1q.x), 0.f) * di;
    h1.y = fmaxf(fmaf(a1.y, di, b1q.y), 0.f) * di;
    h1.z = fmaxf(fmaf(a1.z, di, b1q.z), 0.f) * di;
    h1.w = fmaxf(fmaf(a1.w, di, b1q.w), 0.f) * di;
    float4* op = (float4*)(g_ht2 + (size_t)d * 16 + half * 8);
    op[0] = h0;
    op[1] = h1;
}

// -------- gather layer 2 + fused epilogue: z, s1, s2 --------
__global__ void k_gather2(const float* __restrict__ W2, const float* __restrict__ b2,
                          float* __restrict__ z, int n) {
    __shared__ float4 Ws[16 * 16];   // W2[k] column-quads (4 KB)
    __shared__ float4 bs[16];
    __shared__ float vs1[16], vs2[16];
    for (int i = threadIdx.x; i < 256; i += blockDim.x)
        Ws[i] = ((const float4*)W2)[i];
    if (threadIdx.x < 16) {
        bs[threadIdx.x] = ((const float4*)b2)[threadIdx.x];
        vs1[threadIdx.x] = g_v1[threadIdx.x];
        vs2[threadIdx.x] = g_v2[threadIdx.x];
    }
    __syncthreads();

    int t = blockIdx.x * blockDim.x + threadIdx.x;
    int d = t >> 2, half = (t >> 1) & 1, par = t & 1;
    bool valid = (d < n);
    int dd = valid ? d : 0;

    float4 a0, a1;
    gather_quarter(g_ht2, dd, half, par, a0, a1);
    par_combine(a0, a1);

    float di = g_dinv[dd];
    float mine[8];
    mine[0] = a0.x * di; mine[1] = a0.y * di; mine[2] = a0.z * di; mine[3] = a0.w * di;
    mine[4] = a1.x * di; mine[5] = a1.y * di; mine[6] = a1.z * di; mine[7] = a1.w * di;

    // exchange halves across the (t^2) partner: build full a[16] in every lane
    float a[16];
    #pragma unroll
    for (int j = 0; j < 8; j++) {
        a[half * 8 + j] = mine[j];
        a[(1 - half) * 8 + j] = __shfl_xor_sync(0xffffffffu, mine[j], 2);
    }

    if (!valid) return;

    // head scalars (one lane per node)
    if (half == 0 && par == 0) {
        float s1 = g_c1, s2 = g_c2;
        #pragma unroll
        for (int k = 0; k < 16; k++) {
            s1 = fmaf(a[k], vs1[k], s1);
            s2 = fmaf(a[k], vs2[k], s2);
        }
        g_s1[d] = s1;
        g_s2[d] = s2;
    }

    // z: each of the 4 lanes writes a 16-column quarter (4 float4 quads)
    int quarter = half * 2 + par;
    float4* zp = (float4*)(z + (size_t)d * 64) + quarter * 4;
    #pragma unroll
    for (int q = 0; q < 4; q++) {
        int j4 = quarter * 4 + q;
        float4 acc = bs[j4];
        #pragma unroll
        for (int k = 0; k < 16; k++) {
            float4 w = Ws[k * 16 + j4];
            acc.x = fmaf(a[k], w.x, acc.x);
            acc.y = fmaf(a[k], w.y, acc.y);
            acc.z = fmaf(a[k], w.z, acc.z);
            acc.w = fmaf(a[k], w.w, acc.w);
        }
        zp[q] = acc;
    }
}

// -------- edge logits: s1[src] + s2[dst] + be --------
__global__ void k_logits(const int* __restrict__ ps, const int* __restrict__ pd,
                         const int* __restrict__ ns, const int* __restrict__ nd,
                         const float* __restrict__ be, float* __restrict__ out,
                         int P, int Ng, int n) {
    int i = blockIdx.x * blockDim.x + threadIdx.x;
    if (i >= P + Ng) return;
    unsigned s, d;
    if (i < P) { s = (unsigned)ps[i]; d = (unsigned)pd[i]; }
    else       { s = (unsigned)ns[i - P]; d = (unsigned)nd[i - P]; }
    float v = __ldg(be);
    if (s < (unsigned)n) v += g_s1[s];
    if (d < (unsigned)n) v += g_s2[d];
    out[i] = v;
}

extern "C" void kernel_launch(void* const* d_in, const int* in_sizes, int n_in,
                              void* d_out, int out_size) {
    const float* x  = (const float*)d_in[0];
    const float* W1 = (const float*)d_in[1];
    const float* b1 = (const float*)d_in[2];
    const float* W2 = (const float*)d_in[3];
    const float* b2 = (const float*)d_in[4];
    const float* We = (const float*)d_in[5];
    const float* be = (const float*)d_in[6];
    const int* ei = (const int*)d_in[7];   // edge_index int32 [2, E]
    const int* pe = (const int*)d_in[8];   // pos_edge_index int32 [2, P]
    const int* ne = (const int*)d_in[9];   // neg_edge_index int32 [2, Ng]

    int n  = in_sizes[0] / 512;
    int E  = in_sizes[7] / 2;
    int P  = in_sizes[8] / 2;
    int Ng = in_sizes[9] / 2;

    float* z = (float*)d_out;                 // [n, 64]
    float* logits = z + (size_t)n * 64;       // [P + Ng]

    const int* src = ei;
    const int* dst = ei + E;

    int nb  = (n + 255) / 256;
    int eb  = (E + 255) / 256;
    int gb  = (4 * n + 255) / 256;
    int lb  = (P + Ng + 255) / 256;

    // One-time stream/event setup (outside capture: first call is uncaptured).
    static cudaStream_t s1 = nullptr;
    static cudaEvent_t evFork = nullptr, evG = nullptr;
    if (s1 == nullptr) {
        cudaStreamCreateWithFlags(&s1, cudaStreamNonBlocking);
        cudaEventCreateWithFlags(&evFork, cudaEventDisableTiming);
        cudaEventCreateWithFlags(&evG, cudaEventDisableTiming);
    }

    // Fork at t=0: GEMM1 (raw h, no dinv dependency) overlaps the whole CSR chain.
    cudaEventRecord(evFork, 0);
    cudaStreamWaitEvent(s1, evFork, 0);
    k_gemm1<<<nb, 256, 0, s1>>>(x, W1, n);
    cudaEventRecord(evG, s1);

    // Main stream: CSR build chain.
    k_predeg<<<nb, 256>>>(W2, b2, We, n);
    k_deg_acc<<<eb, 256>>>(dst, E, n);
    k_scan<<<nb, 256>>>(n);
    k_fill<<<eb, 256>>>(src, dst, E, n);

    // Join: scale needs ht1 (gemm1) and dinv (scan).
    cudaStreamWaitEvent(0, evG, 0);
    k_scale<<<nb, 256>>>(n);
    k_gather1<<<gb, 256>>>(b1, n);
    k_gather2<<<gb, 256>>>(W2, b2, z, n);
    k_logits<<<lb, 256>>>(pe, pe + P, ne, ne + Ng, be, logits, P, Ng, n);
}

// round 9
// speedup vs baseline: 1.2013x; 1.0864x over previous
#include <cuda_runtime.h>

#define NMAX 100000
#define EMAX 3200000

// -------- device scratch (no allocations allowed) --------
__device__ int   g_deg[NMAX];          // per-node in-degree (excl self-loop)
__device__ int   g_start[NMAX];        // CSR row start
__device__ int   g_cursor[NMAX];       // fill cursors
__device__ int   g_bsum[512];          // block sums for scan
__device__ int   g_adj[EMAX];          // CSR adjacency: src indices grouped by dst
__device__ float g_dinv[NMAX];         // 1/sqrt(deg+1)
__device__ __align__(16) float g_ht1[NMAX * 16];   // raw x@W1, then dinv-scaled
__device__ __align__(16) float g_ht2[NMAX * 16];   // dinv * relu(agg1+b1)
__device__ __align__(16) float g_agg2[NMAX * 16];  // dinv * (sum ht2)
__device__ float g_s1[NMAX];           // z . We[:64]
__device__ float g_s2[NMAX];           // z . We[64:]
__device__ float g_v1[16];             // W2 @ We[:64]
__device__ float g_v2[16];             // W2 @ We[64:]
__device__ float g_c1, g_c2;           // b2 . We halves

// -------- zero degrees + fold W2/b2 into the edge head --------
__global__ void k_predeg(const float* __restrict__ W2, const float* __restrict__ b2,
                         const float* __restrict__ We, int n) {
    int i = blockIdx.x * blockDim.x + threadIdx.x;
    if (i < n) g_deg[i] = 0;
    if (blockIdx.x == 0) {
        int t = threadIdx.x;
        if (t < 16) {
            float a = 0.f, b = 0.f;
            #pragma unroll
            for (int j = 0; j < 64; j++) {
                float w = W2[t * 64 + j];
                a += w * We[j];
                b += w * We[64 + j];
            }
            g_v1[t] = a;
            g_v2[t] = b;
        } else if (t == 16) {
            float a = 0.f, b = 0.f;
            #pragma unroll
            for (int j = 0; j < 64; j++) {
                a += b2[j] * We[j];
                b += b2[j] * We[64 + j];
            }
            g_c1 = a;
            g_c2 = b;
        }
    }
}

__global__ void k_deg_acc(const int* __restrict__ dst, int E, int n) {
    int e = blockIdx.x * blockDim.x + threadIdx.x;
    if (e < E) {
        unsigned d = (unsigned)dst[e];
        if (d < (unsigned)n) atomicAdd(&g_deg[d], 1);
    }
}

// per-block exclusive scan of g_deg -> g_start (block-local), totals -> g_bsum
__global__ void k_scan1(int n) {
    __shared__ int s[256];
    int tid = threadIdx.x;
    int i = blockIdx.x * 256 + tid;
    int v = (i < n) ? g_deg[i] : 0;
    s[tid] = v;
    __syncthreads();
    #pragma unroll
    for (int o = 1; o < 256; o <<= 1) {
        int t = (tid >= o) ? s[tid - o] : 0;
        __syncthreads();
        s[tid] += t;
        __syncthreads();
    }
    if (i < n) g_start[i] = s[tid] - v;
    if (tid == 255) g_bsum[blockIdx.x] = s[255];
}

// single-block exclusive scan of block sums (nb <= 512)
__global__ void k_scan2(int nb) {
    __shared__ int s[512];
    int tid = threadIdx.x;
    int v = (tid < nb) ? g_bsum[tid] : 0;
    s[tid] = v;
    __syncthreads();
    #pragma unroll
    for (int o = 1; o < 512; o <<= 1) {
        int t = (tid >= o) ? s[tid - o] : 0;
        __syncthreads();
        s[tid] += t;
        __syncthreads();
    }
    if (tid < nb) g_bsum[tid] = s[tid] - v;
}

// finalize: global row starts, cursors, dinv
__global__ void k_scan3(int n) {
    int i = blockIdx.x * blockDim.x + threadIdx.x;
    if (i >= n) return;
    int st = g_start[i] + g_bsum[blockIdx.x];
    g_start[i] = st;
    g_cursor[i] = st;
    g_dinv[i] = rsqrtf((float)g_deg[i] + 1.0f);   // +1 = self-loop
}

__global__ void k_fill(const int* __restrict__ src, const int* __restrict__ dst,
                       int E, int n) {
    int e = blockIdx.x * blockDim.x + threadIdx.x;
    if (e >= E) return;
    unsigned s = (unsigned)src[e];
    unsigned d = (unsigned)dst[e];
    if (s >= (unsigned)n || d >= (unsigned)n) return;
    int slot = atomicAdd(&g_cursor[d], 1);
    g_adj[slot] = (int)s;
}

// -------- GEMM1: ht1 = x @ W1 (raw), coalesced via smem x-tiles --------
__global__ void __launch_bounds__(256) k_gemm1(const float* __restrict__ x,
                                               const float* __restrict__ W1, int n) {
    __shared__ float4 Wss[2048];        // W1[k][4q..4q+3] (32 KB)
    __shared__ float  xs[256 * 12];     // 12 KB padded x tile
    for (int i = threadIdx.x; i < 2048; i += 256)
        Wss[i] = ((const float4*)W1)[i];

    int row0 = blockIdx.x * 256;
    int tid = threadIdx.x;

    float acc[16];
    #pragma unroll
    for (int j = 0; j < 16; j++) acc[j] = 0.f;

    const float4* xq = (const float4*)x;

    for (int kt = 0; kt < 64; kt++) {
        __syncthreads();
        #pragma unroll
        for (int m = 0; m < 2; m++) {
            int idx = tid + m * 256;
            int rr = idx >> 1, q = idx & 1;
            int grow = row0 + rr;
            float4 v = make_float4(0.f, 0.f, 0.f, 0.f);
            if (grow < n) v = __ldg(&xq[(size_t)grow * 128 + kt * 2 + q]);
            *(float4*)&xs[rr * 12 + q * 4] = v;
        }
        __syncthreads();

        float4 x0 = *(const float4*)&xs[tid * 12];
        float4 x1 = *(const float4*)&xs[tid * 12 + 4];
        float xv[8] = {x0.x, x0.y, x0.z, x0.w, x1.x, x1.y, x1.z, x1.w};
        #pragma unroll
        for (int kk = 0; kk < 8; kk++) {
            int k = kt * 8 + kk;
            float xsv = xv[kk];
            #pragma unroll
            for (int q2 = 0; q2 < 4; q2++) {
                float4 w = Wss[k * 4 + q2];
                acc[q2 * 4 + 0] = fmaf(xsv, w.x, acc[q2 * 4 + 0]);
                acc[q2 * 4 + 1] = fmaf(xsv, w.y, acc[q2 * 4 + 1]);
                acc[q2 * 4 + 2] = fmaf(xsv, w.z, acc[q2 * 4 + 2]);
                acc[q2 * 4 + 3] = fmaf(xsv, w.w, acc[q2 * 4 + 3]);
            }
        }
    }

    int r = row0 + tid;
    if (r < n) {
        float4* hp = (float4*)(g_ht1 + (size_t)r * 16);
        #pragma unroll
        for (int q = 0; q < 4; q++)
            hp[q] = make_float4(acc[q * 4 + 0], acc[q * 4 + 1],
                                acc[q * 4 + 2], acc[q * 4 + 3]);
    }
}

// -------- scale: ht1 *= dinv (join of gemm1 stream and CSR chain) --------
__global__ void k_scale(int n) {
    int i = blockIdx.x * blockDim.x + threadIdx.x;
    if (i >= n) return;
    float di = g_dinv[i];
    float4* p = (float4*)(g_ht1 + (size_t)i * 16);
    #pragma unroll
    for (int q = 0; q < 4; q++) {
        float4 v = p[q];
        p[q] = make_float4(v.x * di, v.y * di, v.z * di, v.w * di);
    }
}

// -------- feature-parallel gather core: 16 lanes per node, 1 float/lane --------
__device__ __forceinline__ float gather_feat(const float* __restrict__ ht,
                                             int d, int l) {
    float acc = __ldg(&ht[(size_t)d * 16 + l]);   // self-loop term
    int e = g_start[d];
    int end = e + g_deg[d];
    for (; e + 3 < end; e += 4) {
        int s0 = __ldg(&g_adj[e]);        // broadcast across the 16-lane group
        int s1 = __ldg(&g_adj[e + 1]);
        int s2 = __ldg(&g_adj[e + 2]);
        int s3 = __ldg(&g_adj[e + 3]);
        float v0 = __ldg(&ht[(size_t)s0 * 16 + l]);   // 16 lanes -> one 64B line
        float v1 = __ldg(&ht[(size_t)s1 * 16 + l]);
        float v2 = __ldg(&ht[(size_t)s2 * 16 + l]);
        float v3 = __ldg(&ht[(size_t)s3 * 16 + l]);
        acc += (v0 + v1) + (v2 + v3);
    }
    for (; e < end; e++) {
        int s0 = __ldg(&g_adj[e]);
        acc += __ldg(&ht[(size_t)s0 * 16 + l]);
    }
    return acc;
}

// -------- gather layer 1: ht2 = dinv * relu(dinv*sum + b1) --------
__global__ void k_gather1(const float* __restrict__ b1, int n) {
    int t = blockIdx.x * blockDim.x + threadIdx.x;
    int d = t >> 4, l = t & 15;
    if (d >= n) return;
    float acc = gather_feat(g_ht1, d, l);
    float di = g_dinv[d];
    g_ht2[(size_t)d * 16 + l] = fmaxf(fmaf(acc, di, __ldg(&b1[l])), 0.f) * di;
}

// -------- gather layer 2: agg2 = dinv * sum --------
__global__ void k_gather2(int n) {
    int t = blockIdx.x * blockDim.x + threadIdx.x;
    int d = t >> 4, l = t & 15;
    if (d >= n) return;
    float acc = gather_feat(g_ht2, d, l);
    g_agg2[(size_t)d * 16 + l] = acc * g_dinv[d];
}

// -------- epilogue: z = agg2 @ W2 + b2 ; s1/s2 per-node head scalars --------
__global__ void k_out(const float* __restrict__ W2, const float* __restrict__ b2,
                      float* __restrict__ z, int n) {
    __shared__ float4 Ws[16 * 16];   // W2 rows as float4 quads (4 KB)
    __shared__ float4 bs[16];
    __shared__ float vs1[16], vs2[16];
    for (int i = threadIdx.x; i < 256; i += blockDim.x)
        Ws[i] = ((const float4*)W2)[i];
    if (threadIdx.x < 16) {
        bs[threadIdx.x] = ((const float4*)b2)[threadIdx.x];
        vs1[threadIdx.x] = g_v1[threadIdx.x];
        vs2[threadIdx.x] = g_v2[threadIdx.x];
    }
    __syncthreads();

    int r = blockIdx.x * blockDim.x + threadIdx.x;
    if (r >= n) return;

    float a[16];
    const float4* ag = (const float4*)(g_agg2 + (size_t)r * 16);
    #pragma unroll
    for (int q = 0; q < 4; q++) {
        float4 v = ag[q];
        a[q * 4 + 0] = v.x; a[q * 4 + 1] = v.y; a[q * 4 + 2] = v.z; a[q * 4 + 3] = v.w;
    }

    float s1 = g_c1, s2 = g_c2;
    #pragma unroll
    for (int k = 0; k < 16; k++) {
        s1 = fmaf(a[k], vs1[k], s1);
        s2 = fmaf(a[k], vs2[k], s2);
    }
    g_s1[r] = s1;
    g_s2[r] = s2;

    float4* zp = (float4*)(z + (size_t)r * 64);
    #pragma unroll
    for (int j4 = 0; j4 < 16; j4++) {
        float4 acc = bs[j4];
        #pragma unroll
        for (int k = 0; k < 16; k++) {
            float4 w = Ws[k * 16 + j4];
            acc.x = fmaf(a[k], w.x, acc.x);
            acc.y = fmaf(a[k], w.y, acc.y);
            acc.z = fmaf(a[k], w.z, acc.z);
            acc.w = fmaf(a[k], w.w, acc.w);
        }
        zp[j4] = acc;
    }
}

// -------- edge logits: s1[src] + s2[dst] + be --------
__global__ void k_logits(const int* __restrict__ ps, const int* __restrict__ pd,
                         const int* __restrict__ ns, const int* __restrict__ nd,
                         const float* __restrict__ be, float* __restrict__ out,
                         int P, int Ng, int n) {
    int i = blockIdx.x * blockDim.x + threadIdx.x;
    if (i >= P + Ng) return;
    unsigned s, d;
    if (i < P) { s = (unsigned)ps[i]; d = (unsigned)pd[i]; }
    else       { s = (unsigned)ns[i - P]; d = (unsigned)nd[i - P]; }
    float v = __ldg(be);
    if (s < (unsigned)n) v += g_s1[s];
    if (d < (unsigned)n) v += g_s2[d];
    out[i] = v;
}

extern "C" void kernel_launch(void* const* d_in, const int* in_sizes, int n_in,
                              void* d_out, int out_size) {
    const float* x  = (const float*)d_in[0];
    const float* W1 = (const float*)d_in[1];
    const float* b1 = (const float*)d_in[2];
    const float* W2 = (const float*)d_in[3];
    const float* b2 = (const float*)d_in[4];
    const float* We = (const float*)d_in[5];
    const float* be = (const float*)d_in[6];
    const int* ei = (const int*)d_in[7];   // edge_index int32 [2, E]
    const int* pe = (const int*)d_in[8];   // pos_edge_index int32 [2, P]
    const int* ne = (const int*)d_in[9];   // neg_edge_index int32 [2, Ng]

    int n  = in_sizes[0] / 512;
    int E  = in_sizes[7] / 2;
    int P  = in_sizes[8] / 2;
    int Ng = in_sizes[9] / 2;

    float* z = (float*)d_out;                 // [n, 64]
    float* logits = z + (size_t)n * 64;       // [P + Ng]

    const int* src = ei;
    const int* dst = ei + E;

    int nb  = (n + 255) / 256;
    int eb  = (E + 255) / 256;
    int gb  = (16 * n + 255) / 256;
    int lb  = (P + Ng + 255) / 256;

    // One-time stream/event setup (outside capture: first call is uncaptured).
    static cudaStream_t s1 = nullptr;
    static cudaEvent_t evFork = nullptr, evG = nullptr;
    if (s1 == nullptr) {
        cudaStreamCreateWithFlags(&s1, cudaStreamNonBlocking);
        cudaEventCreateWithFlags(&evFork, cudaEventDisableTiming);
        cudaEventCreateWithFlags(&evG, cudaEventDisableTiming);
    }

    // Fork at t=0: GEMM1 (raw h, no dinv dependency) overlaps the whole CSR chain.
    cudaEventRecord(evFork, 0);
    cudaStreamWaitEvent(s1, evFork, 0);
    k_gemm1<<<nb, 256, 0, s1>>>(x, W1, n);
    cudaEventRecord(evG, s1);

    // Main stream: CSR build chain.
    k_predeg<<<nb, 256>>>(W2, b2, We, n);
    k_deg_acc<<<eb, 256>>>(dst, E, n);
    k_scan1<<<nb, 256>>>(n);
    k_scan2<<<1, 512>>>(nb);
    k_scan3<<<nb, 256>>>(n);
    k_fill<<<eb, 256>>>(src, dst, E, n);

    // Join: scale needs ht1 (gemm1) and dinv (scan).
    cudaStreamWaitEvent(0, evG, 0);
    k_scale<<<nb, 256>>>(n);
    k_gather1<<<gb, 256>>>(b1, n);
    k_gather2<<<gb, 256>>>(n);
    k_out<<<nb, 256>>>(W2, b2, z, n);
    k_logits<<<lb, 256>>>(pe, pe + P, ne, ne + Ng, be, logits, P, Ng, n);
}

// round 10
// speedup vs baseline: 1.2258x; 1.0205x over previous
#include <cuda_runtime.h>

#define NMAX 100000
#define EMAX 3200000

// -------- device scratch (no allocations allowed) --------
// g_deg is zeroed at the END of each call (k_logits); zero-init at load.
__device__ int   g_deg[NMAX];          // per-node in-degree (excl self-loop)
__device__ int   g_start[NMAX];        // CSR row start
__device__ int   g_cursor[NMAX];       // fill cursors
__device__ int   g_bsum[512];          // block sums for scan
__device__ int   g_adj[EMAX];          // CSR adjacency: src indices grouped by dst
__device__ float g_dinv[NMAX];         // 1/sqrt(deg+1)
__device__ __align__(16) float g_ht1[NMAX * 16];   // raw x@W1, then dinv-scaled
__device__ __align__(16) float g_ht2[NMAX * 16];   // dinv * relu(agg1+b1)
__device__ float g_s1[NMAX];           // z . We[:64]
__device__ float g_s2[NMAX];           // z . We[64:]
__device__ float g_v1[16];             // W2 @ We[:64]
__device__ float g_v2[16];             // W2 @ We[64:]
__device__ float g_c1, g_c2;           // b2 . We halves

// -------- degree histogram + (block 0) fold W2/b2 into the edge head --------
__global__ void k_deg_acc(const int* __restrict__ dst, int E, int n,
                          const float* __restrict__ W2, const float* __restrict__ b2,
                          const float* __restrict__ We) {
    if (blockIdx.x == 0) {
        int t = threadIdx.x;
        if (t < 16) {
            float a = 0.f, b = 0.f;
            #pragma unroll
            for (int j = 0; j < 64; j++) {
                float w = W2[t * 64 + j];
                a += w * We[j];
                b += w * We[64 + j];
            }
            g_v1[t] = a;
            g_v2[t] = b;
        } else if (t == 16) {
            float a = 0.f, b = 0.f;
            #pragma unroll
            for (int j = 0; j < 64; j++) {
                a += b2[j] * We[j];
                b += b2[j] * We[64 + j];
            }
            g_c1 = a;
            g_c2 = b;
        }
    }
    int e = blockIdx.x * blockDim.x + threadIdx.x;
    if (e < E) {
        unsigned d = (unsigned)dst[e];
        if (d < (unsigned)n) atomicAdd(&g_deg[d], 1);
    }
}

// per-block exclusive scan of g_deg -> g_start (block-local), totals -> g_bsum
__global__ void k_scan1(int n) {
    __shared__ int s[256];
    int tid = threadIdx.x;
    int i = blockIdx.x * 256 + tid;
    int v = (i < n) ? g_deg[i] : 0;
    s[tid] = v;
    __syncthreads();
    #pragma unroll
    for (int o = 1; o < 256; o <<= 1) {
        int t = (tid >= o) ? s[tid - o] : 0;
        __syncthreads();
        s[tid] += t;
        __syncthreads();
    }
    if (i < n) g_start[i] = s[tid] - v;
    if (tid == 255) g_bsum[blockIdx.x] = s[255];
}

// each block self-computes its running prefix over bsum[0..b-1], finalizes
// global starts, cursors, dinv
__global__ void k_scan23(int n) {
    __shared__ int red[256];
    int tid = threadIdx.x;
    int b = blockIdx.x;
    int partial = 0;
    for (int j = tid; j < b; j += 256) partial += g_bsum[j];
    red[tid] = partial;
    __syncthreads();
    #pragma unroll
    for (int o = 128; o > 0; o >>= 1) {
        if (tid < o) red[tid] += red[tid + o];
        __syncthreads();
    }
    int run = red[0];
    int i = b * 256 + tid;
    if (i < n) {
        int st = g_start[i] + run;
        g_start[i] = st;
        g_cursor[i] = st;
        g_dinv[i] = rsqrtf((float)g_deg[i] + 1.0f);   // +1 = self-loop
    }
}

__global__ void k_fill(const int* __restrict__ src, const int* __restrict__ dst,
                       int E, int n) {
    int e = blockIdx.x * blockDim.x + threadIdx.x;
    if (e >= E) return;
    unsigned s = (unsigned)src[e];
    unsigned d = (unsigned)dst[e];
    if (s >= (unsigned)n || d >= (unsigned)n) return;
    int slot = atomicAdd(&g_cursor[d], 1);
    g_adj[slot] = (int)s;
}

// -------- GEMM1: ht1 = x @ W1 (raw), coalesced via smem x-tiles --------
__global__ void __launch_bounds__(256) k_gemm1(const float* __restrict__ x,
                                               const float* __restrict__ W1, int n) {
    __shared__ float4 Wss[2048];        // W1[k][4q..4q+3] (32 KB)
    __shared__ float  xs[256 * 12];     // 12 KB padded x tile
    for (int i = threadIdx.x; i < 2048; i += 256)
        Wss[i] = ((const float4*)W1)[i];

    int row0 = blockIdx.x * 256;
    int tid = threadIdx.x;

    float acc[16];
    #pragma unroll
    for (int j = 0; j < 16; j++) acc[j] = 0.f;

    const float4* xq = (const float4*)x;

    for (int kt = 0; kt < 64; kt++) {
        __syncthreads();
        #pragma unroll
        for (int m = 0; m < 2; m++) {
            int idx = tid + m * 256;
            int rr = idx >> 1, q = idx & 1;
            int grow = row0 + rr;
            float4 v = make_float4(0.f, 0.f, 0.f, 0.f);
            if (grow < n) v = __ldg(&xq[(size_t)grow * 128 + kt * 2 + q]);
            *(float4*)&xs[rr * 12 + q * 4] = v;
        }
        __syncthreads();

        float4 x0 = *(const float4*)&xs[tid * 12];
        float4 x1 = *(const float4*)&xs[tid * 12 + 4];
        float xv[8] = {x0.x, x0.y, x0.z, x0.w, x1.x, x1.y, x1.z, x1.w};
        #pragma unroll
        for (int kk = 0; kk < 8; kk++) {
            int k = kt * 8 + kk;
            float xsv = xv[kk];
            #pragma unroll
            for (int q2 = 0; q2 < 4; q2++) {
                float4 w = Wss[k * 4 + q2];
                acc[q2 * 4 + 0] = fmaf(xsv, w.x, acc[q2 * 4 + 0]);
                acc[q2 * 4 + 1] = fmaf(xsv, w.y, acc[q2 * 4 + 1]);
                acc[q2 * 4 + 2] = fmaf(xsv, w.z, acc[q2 * 4 + 2]);
                acc[q2 * 4 + 3] = fmaf(xsv, w.w, acc[q2 * 4 + 3]);
            }
        }
    }

    int r = row0 + tid;
    if (r < n) {
        float4* hp = (float4*)(g_ht1 + (size_t)r * 16);
        #pragma unroll
        for (int q = 0; q < 4; q++)
            hp[q] = make_float4(acc[q * 4 + 0], acc[q * 4 + 1],
                                acc[q * 4 + 2], acc[q * 4 + 3]);
    }
}

// -------- scale: ht1 *= dinv (join of gemm1 stream and CSR chain) --------
__global__ void k_scale(int n) {
    int i = blockIdx.x * blockDim.x + threadIdx.x;
    if (i >= n) return;
    float di = g_dinv[i];
    float4* p = (float4*)(g_ht1 + (size_t)i * 16);
    #pragma unroll
    for (int q = 0; q < 4; q++) {
        float4 v = p[q];
        p[q] = make_float4(v.x * di, v.y * di, v.z * di, v.w * di);
    }
}

// -------- feature-parallel gather core: 16 lanes per node, 1 float/lane --------
// unroll 8: 8 independent value LDGs in flight per lane
__device__ __forceinline__ float gather_feat(const float* __restrict__ ht,
                                             int d, int l) {
    float acc = __ldg(&ht[(d << 4) | l]);   // self-loop term
    int e = g_start[d];
    int end = e + g_deg[d];
    for (; e + 7 < end; e += 8) {
        int s0 = __ldg(&g_adj[e]);
        int s1 = __ldg(&g_adj[e + 1]);
        int s2 = __ldg(&g_adj[e + 2]);
        int s3 = __ldg(&g_adj[e + 3]);
        int s4 = __ldg(&g_adj[e + 4]);
        int s5 = __ldg(&g_adj[e + 5]);
        int s6 = __ldg(&g_adj[e + 6]);
        int s7 = __ldg(&g_adj[e + 7]);
        float v0 = __ldg(&ht[(s0 << 4) | l]);
        float v1 = __ldg(&ht[(s1 << 4) | l]);
        float v2 = __ldg(&ht[(s2 << 4) | l]);
        float v3 = __ldg(&ht[(s3 << 4) | l]);
        float v4 = __ldg(&ht[(s4 << 4) | l]);
        float v5 = __ldg(&ht[(s5 << 4) | l]);
        float v6 = __ldg(&ht[(s6 << 4) | l]);
        float v7 = __ldg(&ht[(s7 << 4) | l]);
        acc += ((v0 + v1) + (v2 + v3)) + ((v4 + v5) + (v6 + v7));
    }
    for (; e + 1 < end; e += 2) {
        int s0 = __ldg(&g_adj[e]);
        int s1 = __ldg(&g_adj[e + 1]);
        acc += __ldg(&ht[(s0 << 4) | l]) + __ldg(&ht[(s1 << 4) | l]);
    }
    if (e < end) {
        int s0 = __ldg(&g_adj[e]);
        acc += __ldg(&ht[(s0 << 4) | l]);
    }
    return acc;
}

// -------- gather layer 1: ht2 = dinv * relu(dinv*sum + b1) --------
__global__ void k_gather1(const float* __restrict__ b1, int n) {
    int t = blockIdx.x * blockDim.x + threadIdx.x;
    int d = t >> 4, l = t & 15;
    if (d >= n) return;
    float acc = gather_feat(g_ht1, d, l);
    float di = g_dinv[d];
    g_ht2[(d << 4) | l] = fmaxf(fmaf(acc, di, __ldg(&b1[l])), 0.f) * di;
}

// -------- gather layer 2 + fused epilogue: z, s1, s2 (shuffle exchange) --------
__global__ void k_gather2(const float* __restrict__ W2, const float* __restrict__ b2,
                          float* __restrict__ z, int n) {
    __shared__ float4 Ws[16 * 16];   // W2[k] column-quads (4 KB)
    __shared__ float4 bs[16];
    __shared__ float vs1[16], vs2[16];
    for (int i = threadIdx.x; i < 256; i += blockDim.x)
        Ws[i] = ((const float4*)W2)[i];
    if (threadIdx.x < 16) {
        bs[threadIdx.x] = ((const float4*)b2)[threadIdx.x];
        vs1[threadIdx.x] = g_v1[threadIdx.x];
        vs2[threadIdx.x] = g_v2[threadIdx.x];
    }
    __syncthreads();

    int t = blockIdx.x * blockDim.x + threadIdx.x;
    int d = t >> 4, l = t & 15;
    bool valid = (d < n);

    float acc = 0.f;
    if (valid) acc = gather_feat(g_ht2, d, l) * g_dinv[d];

    // broadcast the 16 per-feature sums to every lane of the group
    int base = (threadIdx.x & 31) & 16;   // group's base lane within the warp
    float a[16];
    #pragma unroll
    for (int k = 0; k < 16; k++)
        a[k] = __shfl_sync(0xffffffffu, acc, base + k, 32);

    if (!valid) return;

    // head scalars: lane 0 -> s1, lane 1 -> s2
    if (l == 0) {
        float s1 = g_c1;
        #pragma unroll
        for (int k = 0; k < 16; k++) s1 = fmaf(a[k], vs1[k], s1);
        g_s1[d] = s1;
    } else if (l == 1) {
        float s2 = g_c2;
        #pragma unroll
        for (int k = 0; k < 16; k++) s2 = fmaf(a[k], vs2[k], s2);
        g_s2[d] = s2;
    }

    // z columns [4l, 4l+4): one float4 per lane, coalesced across the group
    float4 accv = bs[l];
    #pragma unroll
    for (int k = 0; k < 16; k++) {
        float4 w = Ws[k * 16 + l];
        accv.x = fmaf(a[k], w.x, accv.x);
        accv.y = fmaf(a[k], w.y, accv.y);
        accv.z = fmaf(a[k], w.z, accv.z);
        accv.w = fmaf(a[k], w.w, accv.w);
    }
    ((float4*)(z + (size_t)d * 64))[l] = accv;
}

// -------- edge logits: s1[src] + s2[dst] + be ; also re-zero g_deg --------
__global__ void k_logits(const int* __restrict__ ps, const int* __restrict__ pd,
                         const int* __restrict__ ns, const int* __restrict__ nd,
                         const float* __restrict__ be, float* __restrict__ out,
                         int P, int Ng, int n) {
    int i = blockIdx.x * blockDim.x + threadIdx.x;
    if (i < n) g_deg[i] = 0;           // prepare next call (invariant: zero at entry)
    if (i >= P + Ng) return;
    unsigned s, d;
    if (i < P) { s = (unsigned)ps[i]; d = (unsigned)pd[i]; }
    else       { s = (unsigned)ns[i - P]; d = (unsigned)nd[i - P]; }
    float v = __ldg(be);
    if (s < (unsigned)n) v += g_s1[s];
    if (d < (unsigned)n) v += g_s2[d];
    out[i] = v;
}

extern "C" void kernel_launch(void* const* d_in, const int* in_sizes, int n_in,
                              void* d_out, int out_size) {
    const float* x  = (const float*)d_in[0];
    const float* W1 = (const float*)d_in[1];
    const float* b1 = (const float*)d_in[2];
    const float* W2 = (const float*)d_in[3];
    const float* b2 = (const float*)d_in[4];
    const float* We = (const float*)d_in[5];
    const float* be = (const float*)d_in[6];
    const int* ei = (const int*)d_in[7];   // edge_index int32 [2, E]
    const int* pe = (const int*)d_in[8];   // pos_edge_index int32 [2, P]
    const int* ne = (const int*)d_in[9];   // neg_edge_index int32 [2, Ng]

    int n  = in_sizes[0] / 512;
    int E  = in_sizes[7] / 2;
    int P  = in_sizes[8] / 2;
    int Ng = in_sizes[9] / 2;

    float* z = (float*)d_out;                 // [n, 64]
    float* logits = z + (size_t)n * 64;       // [P + Ng]

    const int* src = ei;
    const int* dst = ei + E;

    int nb  = (n + 255) / 256;
    int eb  = (E + 255) / 256;
    int gb  = (16 * n + 255) / 256;
    int lb  = (P + Ng + 255) / 256;

    // One-time stream/event setup (outside capture: first call is uncaptured).
    static cudaStream_t s1 = nullptr;
    static cudaEvent_t evFork = nullptr, evG = nullptr;
    if (s1 == nullptr) {
        cudaStreamCreateWithFlags(&s1, cudaStreamNonBlocking);
        cudaEventCreateWithFlags(&evFork, cudaEventDisableTiming);
        cudaEventCreateWithFlags(&evG, cudaEventDisableTiming);
    }

    // Fork at t=0: GEMM1 (raw h, no dinv dependency) overlaps the whole CSR chain.
    cudaEventRecord(evFork, 0);
    cudaStreamWaitEvent(s1, evFork, 0);
    k_gemm1<<<nb, 256, 0, s1>>>(x, W1, n);
    cudaEventRecord(evG, s1);

    // Main stream: CSR build chain (g_deg is zero on entry, invariant).
    k_deg_acc<<<eb, 256>>>(dst, E, n, W2, b2, We);
    k_scan1<<<nb, 256>>>(n);
    k_scan23<<<nb, 256>>>(n);
    k_fill<<<eb, 256>>>(src, dst, E, n);

    // Join: scale needs ht1 (gemm1) and dinv (scan).
    cudaStreamWaitEvent(0, evG, 0);
    k_scale<<<nb, 256>>>(n);
    k_gather1<<<gb, 256>>>(b1, n);
    k_gather2<<<gb, 256>>>(W2, b2, z, n);
    k_logits<<<lb, 256>>>(pe, pe + P, ne, ne + Ng, be, logits, P, Ng, n);
}